// round 7
// baseline (speedup 1.0000x reference)
#include <cuda_runtime.h>
#include <cuda_bf16.h>
#include <math.h>

#define NPATH 1536
#define NODES 2048
#define SCALE 256.0f   // table nodes per unit radius (delta = 1/256)

// folded radial table: R(rad) * (norm * CG-constant * SH-constant) per path
__device__ float g_tab[(size_t)NODES * NPATH];

// per-path constant fold:
//  p <  256 : block(0,0)  n00*c0          = 1/(4*sqrt(2))
//  p <  512 : block(0,1)  n01*c1/sqrt(3)  = sqrt(3)/(4*sqrt(2))
//  p <  768 : block(1,0)  n10*c1/sqrt(3)  = 1/8
//  p >= 768 : block(1,1), k=(p-768)%3:
//     k=0 (lf=0): n11*c0/sqrt(3) = 1/8
//     k=1 (lf=1): n11*c1/sqrt(6) = 3/(8*sqrt(6))
//     k=2 (lf=2): n11*sqrt(3/(8pi)) = 3/(8*sqrt(2))
__device__ __forceinline__ float foldf(int p) {
    if (p < 256)  return 0.17677669529663687f;
    if (p < 512)  return 0.30618621784789724f;
    if (p < 768)  return 0.125f;
    int k = (p - 768) % 3;
    if (k == 0) return 0.125f;
    if (k == 1) return 0.15309310892394862f;
    return 0.26516504294495533f;
}

// --------------------------------------------------------------------------
// Kernel 1: build folded radial table.
// grid (NODES/8, NPATH/256), 256 threads. 8 radii x 256 paths per block, K=64.
// --------------------------------------------------------------------------
__global__ void __launch_bounds__(256) qm9_build_tab(
    const float* __restrict__ W1, const float* __restrict__ b1,
    const float* __restrict__ W2, const float* __restrict__ b2)
{
    __shared__ float hs[8 * 64];
    const int n0 = blockIdx.x * 8;
    const int p  = blockIdx.y * 256 + threadIdx.x;

    for (int idx = threadIdx.x; idx < 8 * 64; idx += 256) {
        int t = idx >> 6, c = idx & 63;
        float rad = (float)(n0 + t) * (1.0f / SCALE);
        float pre = fmaf(rad, W1[c], b1[c]);
        hs[idx] = pre / (1.0f + expf(-pre));   // silu
    }
    __syncthreads();

    float acc[8];
    const float bb = b2[p];
#pragma unroll
    for (int t = 0; t < 8; t++) acc[t] = bb;

#pragma unroll 8
    for (int c = 0; c < 64; c++) {
        float w = W2[c * NPATH + p];
#pragma unroll
        for (int t = 0; t < 8; t++)
            acc[t] = fmaf(hs[t * 64 + c], w, acc[t]);
    }

    const float f = foldf(p);
#pragma unroll
    for (int t = 0; t < 8; t++)
        g_tab[(size_t)(n0 + t) * NPATH + p] = acc[t] * f;
}

// --------------------------------------------------------------------------
// Kernel 2: per-point kernel assembly. 1 CTA (320 thr) per point.
// Thread -> (row = tid/5, piece = tid%5). piece 0: cols 0..15 (4 float4),
// pieces 1..4: 12 v-aligned cols each (3 float4). Streaming stores.
// Output row layout: rows 0..15 scalar-out u; rows 16..63 = (u,i), i=(y,z,x).
// --------------------------------------------------------------------------
__global__ void __launch_bounds__(320) qm9_assemble(
    const float* __restrict__ rr, float* __restrict__ out)
{
    __shared__ float Rs[NPATH];
    const int pt = blockIdx.x;

    const float x = rr[3 * pt + 0];
    const float y = rr[3 * pt + 1];
    const float z = rr[3 * pt + 2];
    const float r2   = x * x + y * y + z * z;
    const float rinv = rsqrtf(r2);
    // real l=1 basis order (y, z, x)
    const float e0 = y * rinv;
    const float e1 = z * rinv;
    const float e2 = x * rinv;
    const float rad = r2 * rinv;

    // linear interpolation of folded R into smem
    float t = rad * SCALE;
    t = fminf(t, (float)(NODES - 2));
    const int   i0 = (int)t;
    const float fr = t - (float)i0;
    const float* ta = g_tab + (size_t)i0 * NPATH;
    for (int c = threadIdx.x; c < NPATH; c += 320) {
        float a = ta[c];
        float b = ta[c + NPATH];
        Rs[c] = fmaf(fr, b - a, a);
    }
    __syncthreads();

    const int row   = threadIdx.x / 5;
    const int piece = threadIdx.x % 5;

    float4 v4[4];
    float* vals = (float*)v4;
    int ncol;      // number of floats this thread writes
    int col0;      // starting column

    if (row < 16) {
        const int u = row;
        if (piece == 0) {
            // block (0,0): direct copy of folded table values
            const float4* s = (const float4*)(Rs + u * 16);
#pragma unroll
            for (int q = 0; q < 4; q++) v4[q] = s[q];
            ncol = 16; col0 = 0;
        } else {
            // block (0,1): R01[u,v] * e_j
            const int q = piece - 1;          // 0..3, v-groups q*4 .. q*4+3
#pragma unroll
            for (int g = 0; g < 4; g++) {
                const int v = q * 4 + g;
                const float R = Rs[256 + u * 16 + v];
                vals[g * 3 + 0] = R * e0;
                vals[g * 3 + 1] = R * e1;
                vals[g * 3 + 2] = R * e2;
            }
            ncol = 12; col0 = 16 + q * 12;
        }
    } else {
        const int u = (row - 16) / 3;
        const int i = (row - 16) % 3;
        const float ei = (i == 0) ? e0 : (i == 1) ? e1 : e2;

        if (piece == 0) {
            // block (1,0): R10[u,v] * e_i
            const float4* s = (const float4*)(Rs + 512 + u * 16);
#pragma unroll
            for (int q = 0; q < 4; q++) {
                float4 a = s[q];
                a.x *= ei; a.y *= ei; a.z *= ei; a.w *= ei;
                v4[q] = a;
            }
            ncol = 16; col0 = 0;
        } else {
            // block (1,1): K = R0*delta + R1*eps(e) + R2*(e_i e_j - delta/3)
            const float d0 = (i == 0) ? 1.0f : 0.0f;
            const float d1 = (i == 1) ? 1.0f : 0.0f;
            const float d2 = (i == 2) ? 1.0f : 0.0f;
            float E0, E1, E2;                     // E[i][j] = eps_{ijk} e_k
            if (i == 0)      { E0 = 0.0f; E1 =  e2; E2 = -e1; }
            else if (i == 1) { E0 = -e2;  E1 = 0.0f; E2 =  e0; }
            else             { E0 =  e1;  E1 = -e0;  E2 = 0.0f; }
            const float q0 = fmaf(ei, e0, -d0 * (1.0f / 3.0f));
            const float q1 = fmaf(ei, e1, -d1 * (1.0f / 3.0f));
            const float q2 = fmaf(ei, e2, -d2 * (1.0f / 3.0f));

            const int q = piece - 1;
#pragma unroll
            for (int g = 0; g < 4; g++) {
                const int v = q * 4 + g;
                const int base = 768 + (u * 16 + v) * 3;
                const float R0 = Rs[base + 0];
                const float R1 = Rs[base + 1];
                const float R2 = Rs[base + 2];
                vals[g * 3 + 0] = fmaf(R2, q0, fmaf(R1, E0, R0 * d0));
                vals[g * 3 + 1] = fmaf(R2, q1, fmaf(R1, E1, R0 * d1));
                vals[g * 3 + 2] = fmaf(R2, q2, fmaf(R1, E2, R0 * d2));
            }
            ncol = 12; col0 = 16 + q * 12;
        }
    }

    // streaming float4 stores, fully coalesced across the warp
    float4* o = (float4*)(out + (size_t)pt * 4096 + row * 64 + col0);
    const int nq = ncol >> 2;
#pragma unroll
    for (int q = 0; q < 4; q++) {
        if (q < nq) __stcs(o + q, v4[q]);
    }
}

extern "C" void kernel_launch(void* const* d_in, const int* in_sizes, int n_in,
                              void* d_out, int out_size) {
    const float* r  = (const float*)d_in[0];   // (16,32,32,3)
    const float* W1 = (const float*)d_in[1];   // (1,64)
    const float* b1 = (const float*)d_in[2];   // (64,)
    const float* W2 = (const float*)d_in[3];   // (64,1536)
    const float* b2 = (const float*)d_in[4];   // (1536,)
    float* out = (float*)d_out;                // (16,32,32,64,64)

    const int npts = in_sizes[0] / 3;          // 16384

    dim3 gb(NODES / 8, NPATH / 256);           // (256, 6)
    qm9_build_tab<<<gb, 256>>>(W1, b1, W2, b2);
    qm9_assemble<<<npts, 320>>>(r, out);
}

// round 11
// speedup vs baseline: 1.3121x; 1.3121x over previous
#include <cuda_runtime.h>
#include <cuda_bf16.h>
#include <math.h>

#define NPATH 1536
#define NODES 1024
#define SCALE 128.0f   // table nodes per unit radius (delta = 1/128)

// folded radial table: R(rad) * (norm * CG-constant * SH-constant) per path
__device__ float g_tab[(size_t)NODES * NPATH];

__device__ __forceinline__ float foldf(int p) {
    if (p < 256)  return 0.17677669529663687f;   // blk(0,0)
    if (p < 512)  return 0.30618621784789724f;   // blk(0,1)
    if (p < 768)  return 0.125f;                 // blk(1,0)
    int k = (p - 768) % 3;
    if (k == 0) return 0.125f;                   // blk(1,1) lf=0
    if (k == 1) return 0.15309310892394862f;     // blk(1,1) lf=1
    return 0.26516504294495533f;                 // blk(1,1) lf=2
}

// --------------------------------------------------------------------------
// Kernel 1: build folded radial table. grid (NODES/8, NPATH/256), 256 thr.
// --------------------------------------------------------------------------
__global__ void __launch_bounds__(256) qm9_build_tab(
    const float* __restrict__ W1, const float* __restrict__ b1,
    const float* __restrict__ W2, const float* __restrict__ b2)
{
    __shared__ float hs[8 * 64];
    const int n0 = blockIdx.x * 8;
    const int p  = blockIdx.y * 256 + threadIdx.x;

    for (int idx = threadIdx.x; idx < 8 * 64; idx += 256) {
        int t = idx >> 6, c = idx & 63;
        float rad = (float)(n0 + t) * (1.0f / SCALE);
        float pre = fmaf(rad, W1[c], b1[c]);
        hs[idx] = pre / (1.0f + expf(-pre));   // silu
    }
    __syncthreads();

    float acc[8];
    const float bb = b2[p];
#pragma unroll
    for (int t = 0; t < 8; t++) acc[t] = bb;

#pragma unroll 8
    for (int c = 0; c < 64; c++) {
        float w = W2[c * NPATH + p];
#pragma unroll
        for (int t = 0; t < 8; t++)
            acc[t] = fmaf(hs[t * 64 + c], w, acc[t]);
    }

    const float f = foldf(p);
#pragma unroll
    for (int t = 0; t < 8; t++)
        g_tab[(size_t)(n0 + t) * NPATH + p] = acc[t] * f;
}

// --------------------------------------------------------------------------
// Per-point tile writer: thread (rbase = tid/16, q = tid%16) writes one
// float4 at (row, cols 4q..4q+3) for rows rbase, rbase+16, rbase+32,
// rbase+48. Warp lanes cover 2 full contiguous rows -> 512B per STG (ideal).
// --------------------------------------------------------------------------
__device__ __forceinline__ void do_point(
    const float* __restrict__ R, float* __restrict__ outp,
    float e0, float e1, float e2, int rbase, int q)
{
    const int s  = (q - 1) % 3;          // only used when q >= 4
    const int vb = (4 * q - 16) / 3;

    // ---- row rbase (scalar-out u = rbase) ----
    {
        float4 v;
        if (q < 4) {
            v = *(const float4*)(R + rbase * 16 + 4 * q);   // blk(0,0) direct
        } else {
            const float* B = R + 256 + rbase * 16 + vb;     // blk(0,1)
            if (s == 0)      { v.x = B[0]*e0; v.y = B[0]*e1; v.z = B[0]*e2; v.w = B[1]*e0; }
            else if (s == 1) { v.x = B[0]*e1; v.y = B[0]*e2; v.z = B[1]*e0; v.w = B[1]*e1; }
            else             { v.x = B[0]*e2; v.y = B[1]*e0; v.z = B[1]*e1; v.w = B[1]*e2; }
        }
        __stcs((float4*)(outp + rbase * 64 + 4 * q), v);
    }

    // ---- rows rbase+16k, k=1..3 (vector-out: vec = rbase+16(k-1)) ----
#pragma unroll
    for (int k = 1; k < 4; k++) {
        const int vec = rbase + 16 * (k - 1);   // 0..47
        const int u   = vec / 3;
        const int i   = vec - 3 * u;
        const float ei = (i == 0) ? e0 : (i == 1) ? e1 : e2;
        float4 v;
        if (q < 4) {
            v = *(const float4*)(R + 512 + u * 16 + 4 * q); // blk(1,0)
            v.x *= ei; v.y *= ei; v.z *= ei; v.w *= ei;
        } else {
            // blk(1,1): K = R0*delta + R1*eps(e) + R2*(e_i e_j - delta/3)
            const float D0 = (i == 0) ? 1.0f : 0.0f;
            const float D1 = (i == 1) ? 1.0f : 0.0f;
            const float D2 = (i == 2) ? 1.0f : 0.0f;
            float F0, F1, F2;                    // eps_{ijk} e_k, basis (y,z,x)
            if (i == 0)      { F0 = 0.0f; F1 =  e2; F2 = -e1; }
            else if (i == 1) { F0 = -e2;  F1 = 0.0f; F2 =  e0; }
            else             { F0 =  e1;  F1 = -e0;  F2 = 0.0f; }
            const float Q0 = fmaf(ei, e0, -D0 * (1.0f / 3.0f));
            const float Q1 = fmaf(ei, e1, -D1 * (1.0f / 3.0f));
            const float Q2 = fmaf(ei, e2, -D2 * (1.0f / 3.0f));

            const float* B = R + 768 + (u * 16 + vb) * 3;
#define EL(add, Dj, Fj, Qj) fmaf(B[3*(add)+2], Qj, fmaf(B[3*(add)+1], Fj, B[3*(add)] * Dj))
            if (s == 0)      { v.x = EL(0,D0,F0,Q0); v.y = EL(0,D1,F1,Q1); v.z = EL(0,D2,F2,Q2); v.w = EL(1,D0,F0,Q0); }
            else if (s == 1) { v.x = EL(0,D1,F1,Q1); v.y = EL(0,D2,F2,Q2); v.z = EL(1,D0,F0,Q0); v.w = EL(1,D1,F1,Q1); }
            else             { v.x = EL(0,D2,F2,Q2); v.y = EL(1,D0,F0,Q0); v.z = EL(1,D1,F1,Q1); v.w = EL(1,D2,F2,Q2); }
#undef EL
        }
        __stcs((float4*)(outp + (rbase + 16 * k) * 64 + 4 * q), v);
    }
}

// --------------------------------------------------------------------------
// Kernel 2: assembly, 2 points per CTA, 256 threads.
// --------------------------------------------------------------------------
__global__ void __launch_bounds__(256) qm9_assemble(
    const float* __restrict__ rr, float* __restrict__ out, int npts)
{
    __shared__ float Rs[2 * NPATH];
    const int tid = threadIdx.x;
    const int pt0 = blockIdx.x * 2;
    const int pt1 = pt0 + 1;
    const bool has1 = (pt1 < npts);

    // point 0 params
    const float x0 = rr[3 * pt0 + 0], y0 = rr[3 * pt0 + 1], z0 = rr[3 * pt0 + 2];
    const float r20 = x0 * x0 + y0 * y0 + z0 * z0;
    const float ri0 = rsqrtf(r20);
    const float a0 = y0 * ri0, a1 = z0 * ri0, a2 = x0 * ri0;
    float t0 = fminf(r20 * ri0 * SCALE, (float)(NODES - 2));
    const int   i00 = (int)t0;
    const float fr0 = t0 - (float)i00;

    // point 1 params
    float b0 = 0.f, b1 = 0.f, b2 = 0.f, fr1 = 0.f;
    int i01 = 0;
    if (has1) {
        const float x1 = rr[3 * pt1 + 0], y1 = rr[3 * pt1 + 1], z1 = rr[3 * pt1 + 2];
        const float r21 = x1 * x1 + y1 * y1 + z1 * z1;
        const float ri1 = rsqrtf(r21);
        b0 = y1 * ri1; b1 = z1 * ri1; b2 = x1 * ri1;
        float t1 = fminf(r21 * ri1 * SCALE, (float)(NODES - 2));
        i01 = (int)t1;
        fr1 = t1 - (float)i01;
    }

    // interpolate both points' folded R into smem
    {
        const float* ta = g_tab + (size_t)i00 * NPATH;
#pragma unroll
        for (int c = tid; c < NPATH; c += 256) {
            float a = ta[c], b = ta[c + NPATH];
            Rs[c] = fmaf(fr0, b - a, a);
        }
    }
    if (has1) {
        const float* ta = g_tab + (size_t)i01 * NPATH;
#pragma unroll
        for (int c = tid; c < NPATH; c += 256) {
            float a = ta[c], b = ta[c + NPATH];
            Rs[NPATH + c] = fmaf(fr1, b - a, a);
        }
    }
    __syncthreads();

    const int rbase = tid >> 4;      // 0..15
    const int q     = tid & 15;      // 0..15

    do_point(Rs, out + (size_t)pt0 * 4096, a0, a1, a2, rbase, q);
    if (has1)
        do_point(Rs + NPATH, out + (size_t)pt1 * 4096, b0, b1, b2, rbase, q);
}

extern "C" void kernel_launch(void* const* d_in, const int* in_sizes, int n_in,
                              void* d_out, int out_size) {
    const float* r  = (const float*)d_in[0];   // (16,32,32,3)
    const float* W1 = (const float*)d_in[1];   // (1,64)
    const float* b1 = (const float*)d_in[2];   // (64,)
    const float* W2 = (const float*)d_in[3];   // (64,1536)
    const float* b2 = (const float*)d_in[4];   // (1536,)
    float* out = (float*)d_out;                // (16,32,32,64,64)

    const int npts = in_sizes[0] / 3;          // 16384

    dim3 gb(NODES / 8, NPATH / 256);           // (128, 6)
    qm9_build_tab<<<gb, 256>>>(W1, b1, W2, b2);
    qm9_assemble<<<(npts + 1) / 2, 256>>>(r, out, npts);
}

// round 12
// speedup vs baseline: 1.7902x; 1.3644x over previous
#include <cuda_runtime.h>
#include <cuda_bf16.h>
#include <math.h>

#define NPATH 1536
#define NODES 512
#define SCALE 64.0f    // table nodes per unit radius (delta = 1/64)
#define TRAD  16       // radii per build CTA

// folded radial table. Layout per node (permuted vs path order):
//  [0,256)    blk(0,0)  R00[u*16+v]
//  [256,512)  blk(0,1)  R01[u*16+v]
//  [512,768)  blk(1,0)  R10[u*16+v]
//  [768,1024) blk(1,1) lf=0 plane  R0[u*16+v]
//  [1024,1280) blk(1,1) lf=1 plane R1[u*16+v]
//  [1280,1536) blk(1,1) lf=2 plane R2[u*16+v]
__device__ float g_tab[(size_t)NODES * NPATH];

__device__ __forceinline__ float foldf(int p) {
    if (p < 256)  return 0.17677669529663687f;   // blk(0,0)
    if (p < 512)  return 0.30618621784789724f;   // blk(0,1)
    if (p < 768)  return 0.125f;                 // blk(1,0)
    int k = (p - 768) % 3;
    if (k == 0) return 0.125f;                   // blk(1,1) lf=0
    if (k == 1) return 0.15309310892394862f;     // blk(1,1) lf=1
    return 0.26516504294495533f;                 // blk(1,1) lf=2
}

// --------------------------------------------------------------------------
// Kernel 1: build folded radial table (SoA-permuted blk(1,1) region).
// grid (NODES/TRAD, NPATH/256), 256 threads.
// --------------------------------------------------------------------------
__global__ void __launch_bounds__(256) qm9_build_tab(
    const float* __restrict__ W1, const float* __restrict__ b1,
    const float* __restrict__ W2, const float* __restrict__ b2)
{
    __shared__ float hs[TRAD * 64];
    const int n0 = blockIdx.x * TRAD;
    const int p  = blockIdx.y * 256 + threadIdx.x;

    for (int idx = threadIdx.x; idx < TRAD * 64; idx += 256) {
        int t = idx >> 6, c = idx & 63;
        float rad = (float)(n0 + t) * (1.0f / SCALE);
        float pre = fmaf(rad, W1[c], b1[c]);
        hs[idx] = pre / (1.0f + expf(-pre));   // silu
    }
    __syncthreads();

    float acc[TRAD];
    const float bb = b2[p];
#pragma unroll
    for (int t = 0; t < TRAD; t++) acc[t] = bb;

#pragma unroll 4
    for (int c = 0; c < 64; c++) {
        float w = W2[c * NPATH + p];
#pragma unroll
        for (int t = 0; t < TRAD; t++)
            acc[t] = fmaf(hs[t * 64 + c], w, acc[t]);
    }

    // permuted destination index (SoA for blk(1,1))
    int idxp;
    if (p < 768) idxp = p;
    else {
        int k  = (p - 768) % 3;
        int uv = (p - 768) / 3;
        idxp = 768 + k * 256 + uv;
    }
    const float f = foldf(p);
#pragma unroll
    for (int t = 0; t < TRAD; t++)
        g_tab[(size_t)(n0 + t) * NPATH + idxp] = acc[t] * f;
}

// --------------------------------------------------------------------------
// Per-point tile writer. Thread (t = tid/16, q = tid%16) writes one float4
// (cols 4q..4q+3) in rows t, 16+3t, 16+3t+1, 16+3t+2. The 3 vector rows
// share u = t and have COMPILE-TIME i = 0,1,2: no selects, R-values loaded
// once and reused. Warp stores stay 256B-dense per 16 lanes.
// --------------------------------------------------------------------------
__device__ __forceinline__ void do_point(
    const float* __restrict__ R, float* __restrict__ outp,
    float e0, float e1, float e2, int t, int q)
{
    float* os = outp + t * 64 + 4 * q;            // scalar row
    float* ov = outp + (16 + 3 * t) * 64 + 4 * q; // first vector row

    if (q < 4) {
        // cols 0..15
        float4 v = *(const float4*)(R + t * 16 + 4 * q);          // blk(0,0)
        __stcs((float4*)os, v);
        float4 w = *(const float4*)(R + 512 + t * 16 + 4 * q);    // blk(1,0)
        float4 v0 = {w.x * e0, w.y * e0, w.z * e0, w.w * e0};
        float4 v1 = {w.x * e1, w.y * e1, w.z * e1, w.w * e1};
        float4 v2 = {w.x * e2, w.y * e2, w.z * e2, w.w * e2};
        __stcs((float4*)(ov),       v0);
        __stcs((float4*)(ov + 64),  v1);
        __stcs((float4*)(ov + 128), v2);
    } else {
        const int m  = 4 * q - 16;     // 0..44
        const int vb = m / 3;
        const int s  = m % 3;

        // ---- scalar row: blk(0,1) ----
        {
            const float* B = R + 256 + t * 16 + vb;
            const float B0 = B[0], B1 = B[1];
            float4 v;
            if (s == 0)      { v.x = B0*e0; v.y = B0*e1; v.z = B0*e2; v.w = B1*e0; }
            else if (s == 1) { v.x = B0*e1; v.y = B0*e2; v.z = B1*e0; v.w = B1*e1; }
            else             { v.x = B0*e2; v.y = B1*e0; v.z = B1*e1; v.w = B1*e2; }
            __stcs((float4*)os, v);
        }

        // ---- vector rows: blk(1,1), K = R0*delta + R1*eps(e) + R2*(ee^T - delta/3)
        const int base = 768 + t * 16 + vb;
        const float a0 = R[base],       a1 = R[base + 1];     // R0 plane
        const float b0 = R[base + 256], b1 = R[base + 257];   // R1 plane
        const float c0 = R[base + 512], c1 = R[base + 513];   // R2 plane

        const float q00 = fmaf(e0, e0, -1.0f / 3.0f);
        const float q01 = e0 * e1;
        const float q02 = e0 * e2;
        const float q11 = fmaf(e1, e1, -1.0f / 3.0f);
        const float q12 = e1 * e2;
        const float q22 = fmaf(e2, e2, -1.0f / 3.0f);

        // DE(Av,Cv,Qv): diagonal element; OE(Bv,Ev,Cv,Qv): off-diagonal
#define DE(Av, Cv, Qv)      fmaf(Cv, Qv, Av)
#define OE(Bv, Ev, Cv, Qv)  fmaf(Cv, Qv, (Bv) * (Ev))
        float4 r0, r1, r2;
        if (s == 0) {
            // (v,j) = (0,0) (0,1) (0,2) (1,0)
            r0.x = DE(a0, c0, q00); r0.y = OE(b0,  e2, c0, q01); r0.z = OE(b0, -e1, c0, q02); r0.w = DE(a1, c1, q00);
            r1.x = OE(b0, -e2, c0, q01); r1.y = DE(a0, c0, q11); r1.z = OE(b0,  e0, c0, q12); r1.w = OE(b1, -e2, c1, q01);
            r2.x = OE(b0,  e1, c0, q02); r2.y = OE(b0, -e0, c0, q12); r2.z = DE(a0, c0, q22); r2.w = OE(b1,  e1, c1, q02);
        } else if (s == 1) {
            // (v,j) = (0,1) (0,2) (1,0) (1,1)
            r0.x = OE(b0,  e2, c0, q01); r0.y = OE(b0, -e1, c0, q02); r0.z = DE(a1, c1, q00); r0.w = OE(b1,  e2, c1, q01);
            r1.x = DE(a0, c0, q11); r1.y = OE(b0,  e0, c0, q12); r1.z = OE(b1, -e2, c1, q01); r1.w = DE(a1, c1, q11);
            r2.x = OE(b0, -e0, c0, q12); r2.y = DE(a0, c0, q22); r2.z = OE(b1,  e1, c1, q02); r2.w = OE(b1, -e0, c1, q12);
        } else {
            // (v,j) = (0,2) (1,0) (1,1) (1,2)
            r0.x = OE(b0, -e1, c0, q02); r0.y = DE(a1, c1, q00); r0.z = OE(b1,  e2, c1, q01); r0.w = OE(b1, -e1, c1, q02);
            r1.x = OE(b0,  e0, c0, q12); r1.y = OE(b1, -e2, c1, q01); r1.z = DE(a1, c1, q11); r1.w = OE(b1,  e0, c1, q12);
            r2.x = DE(a0, c0, q22); r2.y = OE(b1,  e1, c1, q02); r2.z = OE(b1, -e0, c1, q12); r2.w = DE(a1, c1, q22);
        }
#undef DE
#undef OE
        __stcs((float4*)(ov),       r0);
        __stcs((float4*)(ov + 64),  r1);
        __stcs((float4*)(ov + 128), r2);
    }
}

// --------------------------------------------------------------------------
// Kernel 2: assembly, 2 points per CTA, 256 threads.
// --------------------------------------------------------------------------
__global__ void __launch_bounds__(256) qm9_assemble(
    const float* __restrict__ rr, float* __restrict__ out, int npts)
{
    __shared__ float Rs[2 * NPATH];
    const int tid = threadIdx.x;
    const int pt0 = blockIdx.x * 2;
    const int pt1 = pt0 + 1;
    const bool has1 = (pt1 < npts);

    // point 0 params
    const float x0 = rr[3 * pt0 + 0], y0 = rr[3 * pt0 + 1], z0 = rr[3 * pt0 + 2];
    const float r20 = x0 * x0 + y0 * y0 + z0 * z0;
    const float ri0 = rsqrtf(r20);
    const float a0 = y0 * ri0, a1 = z0 * ri0, a2 = x0 * ri0;  // basis (y,z,x)
    float t0 = fminf(r20 * ri0 * SCALE, (float)(NODES - 2));
    const int   i00 = (int)t0;
    const float fr0 = t0 - (float)i00;

    // point 1 params
    float b0 = 0.f, b1 = 0.f, b2 = 0.f, fr1 = 0.f;
    int i01 = 0;
    if (has1) {
        const float x1 = rr[3 * pt1 + 0], y1 = rr[3 * pt1 + 1], z1 = rr[3 * pt1 + 2];
        const float r21 = x1 * x1 + y1 * y1 + z1 * z1;
        const float ri1 = rsqrtf(r21);
        b0 = y1 * ri1; b1 = z1 * ri1; b2 = x1 * ri1;
        float t1 = fminf(r21 * ri1 * SCALE, (float)(NODES - 2));
        i01 = (int)t1;
        fr1 = t1 - (float)i01;
    }

    // vectorized interpolation of folded R into smem (float4 granularity)
    {
        const float4* ta = (const float4*)(g_tab + (size_t)i00 * NPATH);
        float4* dst = (float4*)Rs;
        for (int c = tid; c < NPATH / 4; c += 256) {
            float4 a = ta[c], b = ta[c + NPATH / 4];
            float4 v;
            v.x = fmaf(fr0, b.x - a.x, a.x);
            v.y = fmaf(fr0, b.y - a.y, a.y);
            v.z = fmaf(fr0, b.z - a.z, a.z);
            v.w = fmaf(fr0, b.w - a.w, a.w);
            dst[c] = v;
        }
    }
    if (has1) {
        const float4* ta = (const float4*)(g_tab + (size_t)i01 * NPATH);
        float4* dst = (float4*)(Rs + NPATH);
        for (int c = tid; c < NPATH / 4; c += 256) {
            float4 a = ta[c], b = ta[c + NPATH / 4];
            float4 v;
            v.x = fmaf(fr1, b.x - a.x, a.x);
            v.y = fmaf(fr1, b.y - a.y, a.y);
            v.z = fmaf(fr1, b.z - a.z, a.z);
            v.w = fmaf(fr1, b.w - a.w, a.w);
            dst[c] = v;
        }
    }
    __syncthreads();

    const int t = tid >> 4;      // 0..15
    const int q = tid & 15;      // 0..15

    do_point(Rs, out + (size_t)pt0 * 4096, a0, a1, a2, t, q);
    if (has1)
        do_point(Rs + NPATH, out + (size_t)pt1 * 4096, b0, b1, b2, t, q);
}

extern "C" void kernel_launch(void* const* d_in, const int* in_sizes, int n_in,
                              void* d_out, int out_size) {
    const float* r  = (const float*)d_in[0];   // (16,32,32,3)
    const float* W1 = (const float*)d_in[1];   // (1,64)
    const float* b1 = (const float*)d_in[2];   // (64,)
    const float* W2 = (const float*)d_in[3];   // (64,1536)
    const float* b2 = (const float*)d_in[4];   // (1536,)
    float* out = (float*)d_out;                // (16,32,32,64,64)

    const int npts = in_sizes[0] / 3;          // 16384

    dim3 gb(NODES / TRAD, NPATH / 256);        // (32, 6)
    qm9_build_tab<<<gb, 256>>>(W1, b1, W2, b2);
    qm9_assemble<<<(npts + 1) / 2, 256>>>(r, out, npts);
}